// round 6
// baseline (speedup 1.0000x reference)
#include <cuda_runtime.h>
#include <cstdint>

// ---------------------------------------------------------------------------
// ContrastiveSparsityLoss — fp32 baseline, structured for FFMA-bound conv/GEMM
//
// Pipeline per encode (path in {sparse,dense} x g in {g1,g2,g3}):
//   K1 conv3x3  : x[5,C,256,256] -> g_y1[5,64,256,256]
//   K2 rowstat  : per-(n,o) sum/sumsq of y1
//   K3 bncoef   : BN1 scale/bias (per-sample for sparse, pooled for dense)
//   K4 gemm     : z = w2 @ relu(bn1(y1))  -> g_z[5,128,256,256]
//   K5 rowstat  : per-(n,oc) sum/sumsq of z
//   K6 bncoef   : BN2 scale/bias
//   K7 feat     : feat[n,oc] = mean_pix relu(bn2(z))
// Then one single-block loss kernel does normalize/sims/logsumexp/mask-count.
// ---------------------------------------------------------------------------

__device__ float g_y1[5 * 64 * 65536];    // 83.9 MB scratch
__device__ float g_z [5 * 128 * 65536];   // 167.8 MB scratch
__device__ float g_stat1[5 * 64 * 2];
__device__ float g_stat2[5 * 128 * 2];
__device__ float g_a1[5 * 64];
__device__ float g_b1[5 * 64];
__device__ float g_a2[5 * 128];
__device__ float g_b2[5 * 128];
__device__ float g_feat[6 * 5 * 128];     // [e][n][oc], e = path*3+g

// ---------------------------------------------------------------------------
// K1: conv3x3 SAME. Block = 64 outch x 16x16 pixel tile of one sample.
// 256 threads, thread = 8 outch x 8 pixels (register tile).
// ---------------------------------------------------------------------------
__global__ __launch_bounds__(256, 2) void conv3x3_kernel(
    const float* __restrict__ x, const float* __restrict__ w, int Cin)
{
    __shared__ float s_in[8][18][19];   // [ci][row][col], padded col stride
    __shared__ float s_w[8][9][64];     // [ci][k][o]

    const int b   = blockIdx.x;
    const int n   = b >> 8;             // 256 tiles per sample
    const int t   = b & 255;
    const int ty0 = (t >> 4) << 4;
    const int tx0 = (t & 15) << 4;
    const int tid = threadIdx.x;
    const int og  = tid >> 5;           // outch group 0..7 (8 outch each)
    const int pg  = tid & 31;           // pixel group   0..31 (8 px each)
    const int px  = pg & 15;
    const int py0 = pg >> 4;            // 0 or 1; thread rows py0 + 2j

    float acc[8][8];
#pragma unroll
    for (int u = 0; u < 8; u++)
#pragma unroll
        for (int j = 0; j < 8; j++) acc[u][j] = 0.f;

    const int nchunks = Cin >> 3;
    for (int cb = 0; cb < nchunks; cb++) {
        const int ci0 = cb << 3;
        __syncthreads();
        // stage 8-channel 18x18 input patch (zero-padded at borders)
        for (int idx = tid; idx < 8 * 18 * 18; idx += 256) {
            int ci  = idx / 324;
            int rem = idx - ci * 324;
            int r   = rem / 18;
            int col = rem - r * 18;
            int gy = ty0 + r - 1, gx = tx0 + col - 1;
            float v = 0.f;
            if ((unsigned)gy < 256u && (unsigned)gx < 256u)
                v = x[(((size_t)(n * Cin + ci0 + ci)) << 16) + (gy << 8) + gx];
            s_in[ci][r][col] = v;
        }
        // stage weights: w layout [O][Cin][3][3]
        for (int idx = tid; idx < 8 * 9 * 64; idx += 256) {
            int o  = idx / 72;
            int r  = idx - o * 72;
            int ci = r / 9;
            int k  = r - ci * 9;
            s_w[ci][k][o] = w[(size_t)(o * Cin + ci0 + ci) * 9 + k];
        }
        __syncthreads();
#pragma unroll 1
        for (int ci = 0; ci < 8; ci++) {
#pragma unroll
            for (int k = 0; k < 9; k++) {
                const int ky = k / 3, kx = k - 3 * (k / 3);
                float wv[8], iv[8];
#pragma unroll
                for (int u = 0; u < 8; u++) wv[u] = s_w[ci][k][(og << 3) + u];
#pragma unroll
                for (int j = 0; j < 8; j++) iv[j] = s_in[ci][py0 + 2 * j + ky][px + kx];
#pragma unroll
                for (int u = 0; u < 8; u++)
#pragma unroll
                    for (int j = 0; j < 8; j++)
                        acc[u][j] = fmaf(wv[u], iv[j], acc[u][j]);
            }
        }
    }
#pragma unroll
    for (int u = 0; u < 8; u++) {
        const int o = (og << 3) + u;
        float* yp = g_y1 + (((size_t)(n * 64 + o)) << 16);
#pragma unroll
        for (int j = 0; j < 8; j++) {
            const int py = py0 + 2 * j;
            yp[((ty0 + py) << 8) + tx0 + px] = acc[u][j];
        }
    }
}

// ---------------------------------------------------------------------------
// K2/K5: per-row (65536 elems) sum / sumsq. which=0 -> y1, which=1 -> z.
// ---------------------------------------------------------------------------
__global__ __launch_bounds__(256) void rowstat_kernel(int which)
{
    const float* buf = which ? g_z : g_y1;
    float* stat      = which ? g_stat2 : g_stat1;
    const int row = blockIdx.x;
    const float4* p = reinterpret_cast<const float4*>(buf + ((size_t)row << 16));
    float s = 0.f, q = 0.f;
    for (int i = threadIdx.x; i < 16384; i += 256) {
        float4 v = p[i];
        s += v.x + v.y + v.z + v.w;
        q += v.x * v.x + v.y * v.y + v.z * v.z + v.w * v.w;
    }
    __shared__ float rs[256], rq[256];
    rs[threadIdx.x] = s; rq[threadIdx.x] = q;
    __syncthreads();
    for (int st = 128; st > 0; st >>= 1) {
        if (threadIdx.x < st) {
            rs[threadIdx.x] += rs[threadIdx.x + st];
            rq[threadIdx.x] += rq[threadIdx.x + st];
        }
        __syncthreads();
    }
    if (threadIdx.x == 0) { stat[row * 2] = rs[0]; stat[row * 2 + 1] = rq[0]; }
}

// ---------------------------------------------------------------------------
// K3/K6: BN coefficients. h = relu(a*x + b). pooled => batch stats (0,2,3).
// ---------------------------------------------------------------------------
__global__ void bncoef_kernel(const float* __restrict__ gamma,
                              const float* __restrict__ beta,
                              int C, int pooled, int which)
{
    int t = blockIdx.x * blockDim.x + threadIdx.x;
    if (t >= 5 * C) return;
    const float* stat = which ? g_stat2 : g_stat1;
    float* A = which ? g_a2 : g_a1;
    float* B = which ? g_b2 : g_b1;
    int o = t % C;
    float mean, var;
    if (pooled) {
        float s = 0.f, q = 0.f;
        for (int m = 0; m < 5; m++) {
            s += stat[(m * C + o) * 2];
            q += stat[(m * C + o) * 2 + 1];
        }
        const float inv = 1.f / (5.f * 65536.f);
        mean = s * inv; var = q * inv - mean * mean;
    } else {
        const float inv = 1.f / 65536.f;
        mean = stat[t * 2] * inv; var = stat[t * 2 + 1] * inv - mean * mean;
    }
    float a = gamma[o] * rsqrtf(var + 1e-5f);
    A[t] = a;
    B[t] = fmaf(-mean, a, beta[o]);
}

// ---------------------------------------------------------------------------
// K4: z[n,oc,pix] = sum_o w2[oc,o] * relu(a1*y1[n,o,pix]+b1)
// Block = 128 oc x 128 pixels of one sample; thread = 8 oc x 8 pix.
// K (=64) split into 2 chunks of 32 to stay under 48KB static smem.
// ---------------------------------------------------------------------------
__global__ __launch_bounds__(256, 2) void gemm_kernel(const float* __restrict__ w2)
{
    __shared__ float s_h[32][128];
    __shared__ float s_w[32][129];    // padded: conflict-free transposed store
    __shared__ float s_a[64], s_b[64];

    const int blk = blockIdx.x;
    const int n   = blk >> 9;           // 512 pixel-tiles per sample
    const int p0  = (blk & 511) << 7;
    const int tid = threadIdx.x;
    const int ocg  = tid >> 4;          // 0..15 (8 oc each)
    const int pixg = tid & 15;          // 0..15 (pixels pixg + 16j)

    if (tid < 64) { s_a[tid] = g_a1[n * 64 + tid]; s_b[tid] = g_b1[n * 64 + tid]; }

    float acc[8][8];
#pragma unroll
    for (int u = 0; u < 8; u++)
#pragma unroll
        for (int j = 0; j < 8; j++) acc[u][j] = 0.f;

    for (int kc = 0; kc < 2; kc++) {
        const int k0 = kc << 5;
        __syncthreads();
        // stage h = relu(bn1(y1)) tile [32 x 128]
        for (int idx = tid; idx < 32 * 128; idx += 256) {
            int kk = idx >> 7;
            int pc = idx & 127;
            int o  = k0 + kk;
            float v = g_y1[(((size_t)(n * 64 + o)) << 16) + p0 + pc];
            s_h[kk][pc] = fmaxf(fmaf(s_a[o], v, s_b[o]), 0.f);
        }
        // stage w2 half, transposed: s_w[k][oc] = w2[oc*64 + k0 + k]
        for (int idx = tid; idx < 32 * 128; idx += 256) {
            int kk = idx & 31;
            int oc = idx >> 5;
            s_w[kk][oc] = w2[oc * 64 + k0 + kk];
        }
        __syncthreads();
#pragma unroll 8
        for (int k = 0; k < 32; k++) {
            float wv[8], hv[8];
#pragma unroll
            for (int u = 0; u < 8; u++) wv[u] = s_w[k][(ocg << 3) + u];
#pragma unroll
            for (int j = 0; j < 8; j++) hv[j] = s_h[k][pixg + (j << 4)];
#pragma unroll
            for (int u = 0; u < 8; u++)
#pragma unroll
                for (int j = 0; j < 8; j++)
                    acc[u][j] = fmaf(wv[u], hv[j], acc[u][j]);
        }
    }
#pragma unroll
    for (int u = 0; u < 8; u++) {
        const int oc = (ocg << 3) + u;
        float* zp = g_z + (((size_t)(n * 128 + oc)) << 16) + p0;
#pragma unroll
        for (int j = 0; j < 8; j++)
            zp[pixg + (j << 4)] = acc[u][j];
    }
}

// ---------------------------------------------------------------------------
// K7: feat[e][row] = mean_pix relu(a2*z + b2)   (row = n*128+oc)
// ---------------------------------------------------------------------------
__global__ __launch_bounds__(256) void feat_kernel(int e)
{
    const int row = blockIdx.x;   // 0..639
    const float a = g_a2[row], b = g_b2[row];
    const float4* p = reinterpret_cast<const float4*>(g_z + ((size_t)row << 16));
    float s = 0.f;
    for (int i = threadIdx.x; i < 16384; i += 256) {
        float4 v = p[i];
        s += fmaxf(fmaf(a, v.x, b), 0.f) + fmaxf(fmaf(a, v.y, b), 0.f)
           + fmaxf(fmaf(a, v.z, b), 0.f) + fmaxf(fmaf(a, v.w, b), 0.f);
    }
    __shared__ float rs[256];
    rs[threadIdx.x] = s;
    __syncthreads();
    for (int st = 128; st > 0; st >>= 1) {
        if (threadIdx.x < st) rs[threadIdx.x] += rs[threadIdx.x + st];
        __syncthreads();
    }
    if (threadIdx.x == 0) g_feat[e * 640 + row] = rs[0] * (1.f / 65536.f);
}

// ---------------------------------------------------------------------------
// K8: normalize features, similarity logits, masked logsumexp CE, weighted avg
// ---------------------------------------------------------------------------
__global__ void loss_kernel(const int* __restrict__ mask, float* __restrict__ out)
{
    __shared__ float Q[3][5][128];
    __shared__ float Kf[3][5][128];
    __shared__ float S[3][5][5];
    __shared__ float X[3][5][3];
    __shared__ int cnt[12];
    __shared__ float wls[15], wts[15];
    const int tid = threadIdx.x;

    if (tid < 30) {                       // normalize: 30 feature rows
        int path = tid / 15;
        int r = tid % 15;
        int g = r / 5, i = r % 5;
        const float* f = g_feat + ((path * 3 + g) * 5 + i) * 128;
        float nr = 0.f;
        for (int d = 0; d < 128; d++) nr += f[d] * f[d];
        float inv = 1.f / fmaxf(sqrtf(nr), 1e-12f);
        float* dst = path ? &Kf[g][i][0] : &Q[g][i][0];
        for (int d = 0; d < 128; d++) dst[d] = f[d] * inv;
    }
    if (tid < 12) cnt[tid] = 0;
    __syncthreads();

    // decision_mask counts: cnt[g][agent]
    for (int idx = tid; idx < 4 * 128 * 128; idx += blockDim.x) {
        int m = mask[idx];
        if (m >= 1) atomicAdd(&cnt[(m - 1) * 4 + (idx >> 14)], 1);
    }

    if (tid < 75) {                       // S[g,i,j] = Q[g,i].K[g,j]
        int g = tid / 25, i = (tid % 25) / 5, j = tid % 5;
        float s = 0.f;
        for (int d = 0; d < 128; d++) s += Q[g][i][d] * Kf[g][j][d];
        S[g][i][j] = s;
    } else if (tid < 120) {               // X[g,i,h] = Q[g,i].K[h,i]
        int r = tid - 75;
        int g = r / 15, i = (r % 15) / 3, h = r % 3;
        float s = 0.f;
        for (int d = 0; d < 128; d++) s += Q[g][i][d] * Kf[h][i][d];
        X[g][i][h] = s;
    }
    __syncthreads();

    if (tid < 15) {
        int g = tid / 5, i = tid % 5;
        float lg[9];
        lg[0] = S[g][i][i];
        for (int j = 0; j < 5; j++) lg[1 + j] = (j == i) ? -1e9f : S[g][i][j];
        for (int h = 0; h < 3; h++) lg[6 + h] = (h == g) ? -1e9f : X[g][i][h];
        float mx = -3.4e38f;
        for (int r = 0; r < 9; r++) { lg[r] *= 10.f; mx = fmaxf(mx, lg[r]); }  // /TEMP
        float se = 0.f;
        for (int r = 0; r < 9; r++) se += expf(lg[r] - mx);
        float lse = mx + logf(se);
        float lt = lse - lg[0];
        float wgt = (i == 0) ? 0.f : (float)cnt[g * 4 + i - 1];
        wls[tid] = wgt * lt;
        wts[tid] = wgt;
    }
    __syncthreads();
    if (tid == 0) {
        float ws = 0.f, tot = 0.f;
        for (int r = 0; r < 15; r++) { ws += wls[r]; tot += wts[r]; }
        out[0] = (tot > 0.f) ? (ws / fmaxf(tot, 1.f)) : 0.f;
    }
}

// ---------------------------------------------------------------------------
extern "C" void kernel_launch(void* const* d_in, const int* in_sizes, int n_in,
                              void* d_out, int out_size)
{
    (void)in_sizes; (void)n_in; (void)out_size;
    const int Cin[3] = {64, 32, 16};
    for (int path = 0; path < 2; path++) {
        for (int g = 0; g < 3; g++) {
            const float* x  = (const float*)d_in[g * 8 + path];   // 0:sparse 1:dense
            const float* w1 = (const float*)d_in[g * 8 + 2];
            const float* g1 = (const float*)d_in[g * 8 + 3];
            const float* b1 = (const float*)d_in[g * 8 + 4];
            const float* w2 = (const float*)d_in[g * 8 + 5];
            const float* g2 = (const float*)d_in[g * 8 + 6];
            const float* b2 = (const float*)d_in[g * 8 + 7];

            conv3x3_kernel<<<1280, 256>>>(x, w1, Cin[g]);
            rowstat_kernel<<<320, 256>>>(0);
            bncoef_kernel<<<2, 256>>>(g1, b1, 64, path, 0);
            gemm_kernel<<<2560, 256>>>(w2);
            rowstat_kernel<<<640, 256>>>(1);
            bncoef_kernel<<<3, 256>>>(g2, b2, 128, path, 1);
            feat_kernel<<<640, 256>>>(path * 3 + g);
        }
    }
    loss_kernel<<<1, 256>>>((const int*)d_in[24], (float*)d_out);
}

// round 7
// speedup vs baseline: 1.7947x; 1.7947x over previous
#include <cuda_runtime.h>
#include <cstdint>

// ---------------------------------------------------------------------------
// ContrastiveSparsityLoss — fp32, FFMA2-packed conv/GEMM, fused BN stats
//
// Per encode (path in {sparse,dense} x g in {g1,g2,g3}):
//   K0 zero_stats
//   K1 conv3x3  : x[5,C,256,256] -> g_y1[5,64,256,256]   (+ sum/sumsq epilogue)
//   K2 bncoef   : BN1 scale/bias (per-sample sparse, pooled dense)
//   K3 gemm     : z = w2 @ relu(bn1(y1)) -> g_z          (+ sum/sumsq epilogue)
//   K4 bncoef   : BN2 scale/bias
//   K5 feat     : feat[n,oc] = mean_pix relu(bn2(z))
// Then one single-block loss kernel.
// ---------------------------------------------------------------------------

typedef unsigned long long u64;

__device__ __forceinline__ u64 dup2(float v) {
    u64 d; asm("mov.b64 %0, {%1, %1};" : "=l"(d) : "f"(v)); return d;
}
__device__ __forceinline__ void ffma2(u64& c, u64 a, u64 b) {
    asm("fma.rn.f32x2 %0, %1, %2, %0;" : "+l"(c) : "l"(a), "l"(b));
}
__device__ __forceinline__ float2 upk2(u64 v) {
    float2 r; asm("mov.b64 {%0, %1}, %2;" : "=f"(r.x), "=f"(r.y) : "l"(v)); return r;
}

__device__ float g_y1[5 * 64 * 65536];    // 83.9 MB scratch
__device__ float g_z [5 * 128 * 65536];   // 167.8 MB scratch
__device__ float g_stat1[5 * 64 * 2];
__device__ float g_stat2[5 * 128 * 2];
__device__ float g_a1[5 * 64];
__device__ float g_b1[5 * 64];
__device__ float g_a2[5 * 128];
__device__ float g_b2[5 * 128];
__device__ float g_feat[6 * 5 * 128];     // [e][n][oc], e = path*3+g

// ---------------------------------------------------------------------------
__global__ void zero_stats_kernel()
{
    int t = threadIdx.x;
    for (int i = t; i < 640; i += 256)  g_stat1[i] = 0.f;
    for (int i = t; i < 1280; i += 256) g_stat2[i] = 0.f;
}

// ---------------------------------------------------------------------------
// K1: conv3x3 SAME. Block = 64 outch x 16x16 pixel tile of one sample.
// 256 threads, thread = 8 outch (4 packed pairs) x 8 pixels.
// ---------------------------------------------------------------------------
__global__ __launch_bounds__(256, 2) void conv3x3_kernel(
    const float* __restrict__ x, const float* __restrict__ w, int Cin)
{
    __shared__ float s_in[8][18][19];   // [ci][row][col], padded col stride
    __shared__ float s_w[8][9][64];     // [ci][k][o]

    const int b   = blockIdx.x;
    const int n   = b >> 8;             // 256 tiles per sample
    const int t   = b & 255;
    const int ty0 = (t >> 4) << 4;
    const int tx0 = (t & 15) << 4;
    const int tid = threadIdx.x;
    const int og  = tid >> 5;           // outch group 0..7 (8 outch, warp-uniform)
    const int pg  = tid & 31;
    const int px  = pg & 15;
    const int py0 = pg >> 4;            // 0 or 1; thread rows py0 + 2j

    u64 acc[4][8];                      // [oc-pair][pixel]
#pragma unroll
    for (int p = 0; p < 4; p++)
#pragma unroll
        for (int j = 0; j < 8; j++) acc[p][j] = 0ull;

    const int nchunks = Cin >> 3;
    for (int cb = 0; cb < nchunks; cb++) {
        const int ci0 = cb << 3;
        __syncthreads();
        // stage 8-channel 18x18 input patch (zero-padded at borders)
        for (int idx = tid; idx < 8 * 18 * 18; idx += 256) {
            int ci  = idx / 324;
            int rem = idx - ci * 324;
            int r   = rem / 18;
            int col = rem - r * 18;
            int gy = ty0 + r - 1, gx = tx0 + col - 1;
            float v = 0.f;
            if ((unsigned)gy < 256u && (unsigned)gx < 256u)
                v = x[(((size_t)(n * Cin + ci0 + ci)) << 16) + (gy << 8) + gx];
            s_in[ci][r][col] = v;
        }
        // stage weights: w layout [O][Cin][3][3]
        for (int idx = tid; idx < 8 * 9 * 64; idx += 256) {
            int o  = idx / 72;
            int r  = idx - o * 72;
            int ci = r / 9;
            int k  = r - ci * 9;
            s_w[ci][k][o] = w[(size_t)(o * Cin + ci0 + ci) * 9 + k];
        }
        __syncthreads();
#pragma unroll 1
        for (int ci = 0; ci < 8; ci++) {
#pragma unroll
            for (int k = 0; k < 9; k++) {
                const int ky = k / 3, kx = k - 3 * (k / 3);
                u64 wv[4];
#pragma unroll
                for (int p = 0; p < 4; p++)   // aligned LDS.64 weight pairs
                    wv[p] = *reinterpret_cast<const u64*>(&s_w[ci][k][(og << 3) + (p << 1)]);
#pragma unroll
                for (int j = 0; j < 8; j++) {
                    u64 iv = dup2(s_in[ci][py0 + 2 * j + ky][px + kx]);
#pragma unroll
                    for (int p = 0; p < 4; p++) ffma2(acc[p][j], wv[p], iv);
                }
            }
        }
    }

    // epilogue: store y1 + per-(n,o) sum/sumsq partials
    float ss[8], qq[8];
#pragma unroll
    for (int u = 0; u < 8; u++) { ss[u] = 0.f; qq[u] = 0.f; }
#pragma unroll
    for (int p = 0; p < 4; p++) {
        const int o0 = (og << 3) + (p << 1);
        float* yp0 = g_y1 + (((size_t)(n * 64 + o0)) << 16);
        float* yp1 = yp0 + 65536;
#pragma unroll
        for (int j = 0; j < 8; j++) {
            float2 v = upk2(acc[p][j]);
            const int off = ((ty0 + py0 + 2 * j) << 8) + tx0 + px;
            yp0[off] = v.x; yp1[off] = v.y;
            ss[2 * p]     += v.x; qq[2 * p]     += v.x * v.x;
            ss[2 * p + 1] += v.y; qq[2 * p + 1] += v.y * v.y;
        }
    }
    const int lane = tid & 31;
#pragma unroll
    for (int u = 0; u < 8; u++) {
        float s = ss[u], q = qq[u];
#pragma unroll
        for (int off = 16; off > 0; off >>= 1) {
            s += __shfl_down_sync(0xffffffffu, s, off);
            q += __shfl_down_sync(0xffffffffu, q, off);
        }
        if (lane == 0) {
            const int row = (n << 6) + (og << 3) + u;
            atomicAdd(&g_stat1[row * 2],     s);
            atomicAdd(&g_stat1[row * 2 + 1], q);
        }
    }
}

// ---------------------------------------------------------------------------
// K2/K4: BN coefficients. h = relu(a*x + b). pooled => batch stats (0,2,3).
// ---------------------------------------------------------------------------
__global__ void bncoef_kernel(const float* __restrict__ gamma,
                              const float* __restrict__ beta,
                              int C, int pooled, int which)
{
    int t = blockIdx.x * blockDim.x + threadIdx.x;
    if (t >= 5 * C) return;
    const float* stat = which ? g_stat2 : g_stat1;
    float* A = which ? g_a2 : g_a1;
    float* B = which ? g_b2 : g_b1;
    int o = t % C;
    float mean, var;
    if (pooled) {
        float s = 0.f, q = 0.f;
        for (int m = 0; m < 5; m++) {
            s += stat[(m * C + o) * 2];
            q += stat[(m * C + o) * 2 + 1];
        }
        const float inv = 1.f / (5.f * 65536.f);
        mean = s * inv; var = q * inv - mean * mean;
    } else {
        const float inv = 1.f / 65536.f;
        mean = stat[t * 2] * inv; var = stat[t * 2 + 1] * inv - mean * mean;
    }
    float a = gamma[o] * rsqrtf(var + 1e-5f);
    A[t] = a;
    B[t] = fmaf(-mean, a, beta[o]);
}

// ---------------------------------------------------------------------------
// K3: z[n,oc,pix] = sum_o w2[oc,o] * relu(a1*y1[n,o,pix]+b1)
// Block = 128 oc x 128 pixels; thread = 8 oc (4 packed pairs) x 8 pix.
// ---------------------------------------------------------------------------
__global__ __launch_bounds__(256, 2) void gemm_kernel(const float* __restrict__ w2)
{
    __shared__ float s_h[32][128];
    __shared__ float s_w[32][130];    // even padding: aligned LDS.64 oc-pairs
    __shared__ float s_a[64], s_b[64];

    const int blk = blockIdx.x;
    const int n   = blk >> 9;           // 512 pixel-tiles per sample
    const int p0  = (blk & 511) << 7;
    const int tid = threadIdx.x;
    const int ocg  = tid >> 4;          // 0..15 (8 oc each; 2 groups per warp)
    const int pixg = tid & 15;          // pixels pixg + 16j

    if (tid < 64) { s_a[tid] = g_a1[n * 64 + tid]; s_b[tid] = g_b1[n * 64 + tid]; }

    u64 acc[4][8];
#pragma unroll
    for (int p = 0; p < 4; p++)
#pragma unroll
        for (int j = 0; j < 8; j++) acc[p][j] = 0ull;

    for (int kc = 0; kc < 2; kc++) {
        const int k0 = kc << 5;
        __syncthreads();
        // stage h = relu(bn1(y1)) tile [32 x 128]
        for (int idx = tid; idx < 32 * 128; idx += 256) {
            int kk = idx >> 7;
            int pc = idx & 127;
            int o  = k0 + kk;
            float v = g_y1[(((size_t)(n * 64 + o)) << 16) + p0 + pc];
            s_h[kk][pc] = fmaxf(fmaf(s_a[o], v, s_b[o]), 0.f);
        }
        // stage w2 half, transposed: s_w[k][oc] = w2[oc*64 + k0 + k]
        for (int idx = tid; idx < 32 * 128; idx += 256) {
            int kk = idx & 31;
            int oc = idx >> 5;
            s_w[kk][oc] = w2[oc * 64 + k0 + kk];
        }
        __syncthreads();
#pragma unroll 8
        for (int k = 0; k < 32; k++) {
            u64 wv[4];
#pragma unroll
            for (int p = 0; p < 4; p++)
                wv[p] = *reinterpret_cast<const u64*>(&s_w[k][(ocg << 3) + (p << 1)]);
#pragma unroll
            for (int j = 0; j < 8; j++) {
                u64 hv = dup2(s_h[k][pixg + (j << 4)]);
#pragma unroll
                for (int p = 0; p < 4; p++) ffma2(acc[p][j], wv[p], hv);
            }
        }
    }

    // epilogue: store z + per-(n,oc) sum/sumsq partials
    float ss[8], qq[8];
#pragma unroll
    for (int u = 0; u < 8; u++) { ss[u] = 0.f; qq[u] = 0.f; }
#pragma unroll
    for (int p = 0; p < 4; p++) {
        const int oc0 = (ocg << 3) + (p << 1);
        float* zp0 = g_z + (((size_t)(n * 128 + oc0)) << 16) + p0;
        float* zp1 = zp0 + 65536;
#pragma unroll
        for (int j = 0; j < 8; j++) {
            float2 v = upk2(acc[p][j]);
            zp0[pixg + (j << 4)] = v.x;
            zp1[pixg + (j << 4)] = v.y;
            ss[2 * p]     += v.x; qq[2 * p]     += v.x * v.x;
            ss[2 * p + 1] += v.y; qq[2 * p + 1] += v.y * v.y;
        }
    }
    const int lane = tid & 31;
#pragma unroll
    for (int u = 0; u < 8; u++) {
        float s = ss[u], q = qq[u];
#pragma unroll
        for (int off = 8; off > 0; off >>= 1) {   // reduce within 16-lane segment
            s += __shfl_down_sync(0xffffffffu, s, off, 16);
            q += __shfl_down_sync(0xffffffffu, q, off, 16);
        }
        if ((lane & 15) == 0) {
            const int row = n * 128 + (ocg << 3) + u;
            atomicAdd(&g_stat2[row * 2],     s);
            atomicAdd(&g_stat2[row * 2 + 1], q);
        }
    }
}

// ---------------------------------------------------------------------------
// K5: feat[e][row] = mean_pix relu(a2*z + b2)   (row = n*128+oc)
// ---------------------------------------------------------------------------
__global__ __launch_bounds__(256) void feat_kernel(int e)
{
    const int row = blockIdx.x;   // 0..639
    const float a = g_a2[row], b = g_b2[row];
    const float4* p = reinterpret_cast<const float4*>(g_z + ((size_t)row << 16));
    float s = 0.f;
    for (int i = threadIdx.x; i < 16384; i += 256) {
        float4 v = p[i];
        s += fmaxf(fmaf(a, v.x, b), 0.f) + fmaxf(fmaf(a, v.y, b), 0.f)
           + fmaxf(fmaf(a, v.z, b), 0.f) + fmaxf(fmaf(a, v.w, b), 0.f);
    }
    __shared__ float rs[256];
    rs[threadIdx.x] = s;
    __syncthreads();
    for (int st = 128; st > 0; st >>= 1) {
        if (threadIdx.x < st) rs[threadIdx.x] += rs[threadIdx.x + st];
        __syncthreads();
    }
    if (threadIdx.x == 0) g_feat[e * 640 + row] = rs[0] * (1.f / 65536.f);
}

// ---------------------------------------------------------------------------
// K6: normalize features, similarity logits, masked logsumexp CE, weighted avg
// ---------------------------------------------------------------------------
__global__ void loss_kernel(const int* __restrict__ mask, float* __restrict__ out)
{
    __shared__ float Q[3][5][128];
    __shared__ float Kf[3][5][128];
    __shared__ float S[3][5][5];
    __shared__ float X[3][5][3];
    __shared__ int cnt[12];
    __shared__ float wls[15], wts[15];
    const int tid = threadIdx.x;

    if (tid < 30) {                       // normalize: 30 feature rows
        int path = tid / 15;
        int r = tid % 15;
        int g = r / 5, i = r % 5;
        const float* f = g_feat + ((path * 3 + g) * 5 + i) * 128;
        float nr = 0.f;
        for (int d = 0; d < 128; d++) nr += f[d] * f[d];
        float inv = 1.f / fmaxf(sqrtf(nr), 1e-12f);
        float* dst = path ? &Kf[g][i][0] : &Q[g][i][0];
        for (int d = 0; d < 128; d++) dst[d] = f[d] * inv;
    }
    if (tid < 12) cnt[tid] = 0;
    __syncthreads();

    // decision_mask counts: cnt[g][agent]
    for (int idx = tid; idx < 4 * 128 * 128; idx += blockDim.x) {
        int m = mask[idx];
        if (m >= 1) atomicAdd(&cnt[(m - 1) * 4 + (idx >> 14)], 1);
    }

    if (tid < 75) {                       // S[g,i,j] = Q[g,i].K[g,j]
        int g = tid / 25, i = (tid % 25) / 5, j = tid % 5;
        float s = 0.f;
        for (int d = 0; d < 128; d++) s += Q[g][i][d] * Kf[g][j][d];
        S[g][i][j] = s;
    } else if (tid < 120) {               // X[g,i,h] = Q[g,i].K[h,i]
        int r = tid - 75;
        int g = r / 15, i = (r % 15) / 3, h = r % 3;
        float s = 0.f;
        for (int d = 0; d < 128; d++) s += Q[g][i][d] * Kf[h][i][d];
        X[g][i][h] = s;
    }
    __syncthreads();

    if (tid < 15) {
        int g = tid / 5, i = tid % 5;
        float lg[9];
        lg[0] = S[g][i][i];
        for (int j = 0; j < 5; j++) lg[1 + j] = (j == i) ? -1e9f : S[g][i][j];
        for (int h = 0; h < 3; h++) lg[6 + h] = (h == g) ? -1e9f : X[g][i][h];
        float mx = -3.4e38f;
        for (int r = 0; r < 9; r++) { lg[r] *= 10.f; mx = fmaxf(mx, lg[r]); }  // /TEMP
        float se = 0.f;
        for (int r = 0; r < 9; r++) se += expf(lg[r] - mx);
        float lse = mx + logf(se);
        float lt = lse - lg[0];
        float wgt = (i == 0) ? 0.f : (float)cnt[g * 4 + i - 1];
        wls[tid] = wgt * lt;
        wts[tid] = wgt;
    }
    __syncthreads();
    if (tid == 0) {
        float ws = 0.f, tot = 0.f;
        for (int r = 0; r < 15; r++) { ws += wls[r]; tot += wts[r]; }
        out[0] = (tot > 0.f) ? (ws / fmaxf(tot, 1.f)) : 0.f;
    }
}

// ---------------------------------------------------------------------------
extern "C" void kernel_launch(void* const* d_in, const int* in_sizes, int n_in,
                              void* d_out, int out_size)
{
    (void)in_sizes; (void)n_in; (void)out_size;
    const int Cin[3] = {64, 32, 16};
    for (int path = 0; path < 2; path++) {
        for (int g = 0; g < 3; g++) {
            const float* x  = (const float*)d_in[g * 8 + path];   // 0:sparse 1:dense
            const float* w1 = (const float*)d_in[g * 8 + 2];
            const float* g1 = (const float*)d_in[g * 8 + 3];
            const float* b1 = (const float*)d_in[g * 8 + 4];
            const float* w2 = (const float*)d_in[g * 8 + 5];
            const float* g2 = (const float*)d_in[g * 8 + 6];
            const float* b2 = (const float*)d_in[g * 8 + 7];

            zero_stats_kernel<<<1, 256>>>();
            conv3x3_kernel<<<1280, 256>>>(x, w1, Cin[g]);
            bncoef_kernel<<<2, 256>>>(g1, b1, 64, path, 0);
            gemm_kernel<<<2560, 256>>>(w2);
            bncoef_kernel<<<3, 256>>>(g2, b2, 128, path, 1);
            feat_kernel<<<640, 256>>>(path * 3 + g);
        }
    }
    loss_kernel<<<1, 256>>>((const int*)d_in[24], (float*)d_out);
}